// round 2
// baseline (speedup 1.0000x reference)
#include <cuda_runtime.h>
#include <cuda_bf16.h>
#include <math.h>

#define S_LEN   4096
#define DM      1024
#define N3      3072
#define NHEADS  16
#define HD      64
#define WIN     512

// scratch for kqv = x @ w_kqv   (cols 0..1023 = K, 1024..2047 = Q, 2048..3071 = V)
__device__ float g_kqv[S_LEN * N3];

// ---------------------------------------------------------------------------
// Kernel 1: fp32 GEMM  C[4096,3072] = A[4096,1024] @ B[1024,3072]
// 128x128 block tile, BK=16, 256 threads, 8x8 microtile, double-buffered smem.
// ---------------------------------------------------------------------------
__global__ __launch_bounds__(256, 2)
void gemm_kqv_kernel(const float* __restrict__ A, const float* __restrict__ B) {
    __shared__ float As[2][16][132];   // [k][m], padded
    __shared__ float Bs[2][16][128];   // [k][n]

    const int tid = threadIdx.x;
    const int m0 = blockIdx.y * 128;
    const int n0 = blockIdx.x * 128;

    const int a_row = tid >> 2;            // 0..63
    const int a_c4  = (tid & 3) * 4;       // 0,4,8,12
    const int b_row = tid >> 5;            // 0..7
    const int b_c4  = (tid & 31) * 4;      // 0..124

    const int ty = tid >> 4;               // 0..15
    const int tx = tid & 15;               // 0..15

    float acc[8][8];
    #pragma unroll
    for (int i = 0; i < 8; ++i)
        #pragma unroll
        for (int j = 0; j < 8; ++j) acc[i][j] = 0.f;

    float4 pa0, pa1, pb0, pb1;

    // first tile -> buffer 0
    pa0 = *(const float4*)&A[(m0 + a_row) * DM + a_c4];
    pa1 = *(const float4*)&A[(m0 + a_row + 64) * DM + a_c4];
    pb0 = *(const float4*)&B[b_row * N3 + n0 + b_c4];
    pb1 = *(const float4*)&B[(b_row + 8) * N3 + n0 + b_c4];

    As[0][a_c4 + 0][a_row] = pa0.x;
    As[0][a_c4 + 1][a_row] = pa0.y;
    As[0][a_c4 + 2][a_row] = pa0.z;
    As[0][a_c4 + 3][a_row] = pa0.w;
    As[0][a_c4 + 0][a_row + 64] = pa1.x;
    As[0][a_c4 + 1][a_row + 64] = pa1.y;
    As[0][a_c4 + 2][a_row + 64] = pa1.z;
    As[0][a_c4 + 3][a_row + 64] = pa1.w;
    *(float4*)&Bs[0][b_row][b_c4]     = pb0;
    *(float4*)&Bs[0][b_row + 8][b_c4] = pb1;
    __syncthreads();

    const int KT = DM / 16;  // 64
    for (int kt = 0; kt < KT; ++kt) {
        const int buf = kt & 1;
        if (kt + 1 < KT) {
            const int k0 = (kt + 1) * 16;
            pa0 = *(const float4*)&A[(m0 + a_row) * DM + k0 + a_c4];
            pa1 = *(const float4*)&A[(m0 + a_row + 64) * DM + k0 + a_c4];
            pb0 = *(const float4*)&B[(k0 + b_row) * N3 + n0 + b_c4];
            pb1 = *(const float4*)&B[(k0 + b_row + 8) * N3 + n0 + b_c4];
        }
        #pragma unroll
        for (int k = 0; k < 16; ++k) {
            float4 x0 = *(const float4*)&As[buf][k][ty * 8];
            float4 x1 = *(const float4*)&As[buf][k][ty * 8 + 4];
            float4 y0 = *(const float4*)&Bs[buf][k][tx * 8];
            float4 y1 = *(const float4*)&Bs[buf][k][tx * 8 + 4];
            float xa[8] = {x0.x, x0.y, x0.z, x0.w, x1.x, x1.y, x1.z, x1.w};
            float yb[8] = {y0.x, y0.y, y0.z, y0.w, y1.x, y1.y, y1.z, y1.w};
            #pragma unroll
            for (int i = 0; i < 8; ++i)
                #pragma unroll
                for (int j = 0; j < 8; ++j)
                    acc[i][j] += xa[i] * yb[j];
        }
        if (kt + 1 < KT) {
            const int nb = buf ^ 1;
            As[nb][a_c4 + 0][a_row] = pa0.x;
            As[nb][a_c4 + 1][a_row] = pa0.y;
            As[nb][a_c4 + 2][a_row] = pa0.z;
            As[nb][a_c4 + 3][a_row] = pa0.w;
            As[nb][a_c4 + 0][a_row + 64] = pa1.x;
            As[nb][a_c4 + 1][a_row + 64] = pa1.y;
            As[nb][a_c4 + 2][a_row + 64] = pa1.z;
            As[nb][a_c4 + 3][a_row + 64] = pa1.w;
            *(float4*)&Bs[nb][b_row][b_c4]     = pb0;
            *(float4*)&Bs[nb][b_row + 8][b_c4] = pb1;
        }
        __syncthreads();
    }

    #pragma unroll
    for (int i = 0; i < 8; ++i) {
        float4 o0 = make_float4(acc[i][0], acc[i][1], acc[i][2], acc[i][3]);
        float4 o1 = make_float4(acc[i][4], acc[i][5], acc[i][6], acc[i][7]);
        float* crow = &g_kqv[(m0 + ty * 8 + i) * N3 + n0 + tx * 8];
        *(float4*)&crow[0] = o0;
        *(float4*)&crow[4] = o1;
    }
}

// ---------------------------------------------------------------------------
// Kernel 2: sliding-window ALiBi attention with online softmax.
// Block = (64-query tile, head). 256 threads: quad = tid/64 (key slice),
// q = tid%64 (query). All K/V smem reads are warp-uniform (broadcast).
// Each thread accumulates full 64-dim output over its 16-key slice;
// cross-quad reduction at the end.
// ---------------------------------------------------------------------------
__global__ __launch_bounds__(256, 2)
void attn_alibi_kernel(float* __restrict__ out) {
    extern __shared__ float sm[];
    float* Qs   = sm;            // [d][q]   64*64  (transposed)
    float* Ks   = sm + 4096;     // [key][d] 64*64
    float* Vs   = sm + 8192;     // [key][d] 64*64
    float* redM = sm + 12288;    // 256
    float* redL = sm + 12544;    // 256
    float* Osum = sm;            // overlay (Q/K dead at that point): [q][65]

    const int tid  = threadIdx.x;
    const int quad = tid >> 6;       // 0..3
    const int q    = tid & 63;       // 0..63
    const int key0 = quad * 16;
    const int i0   = blockIdx.x * 64;
    const int h    = blockIdx.y;
    const int i    = i0 + q;
    const float slope = exp2f(-0.5f * (float)(h + 1));   // 1/((2^8)^((h+1)/16))

    // load Q tile, transposed and pre-scaled by 1/sqrt(d_model) = 1/32
    for (int idx = tid; idx < 4096; idx += 256) {
        int r = idx >> 6, c = idx & 63;
        Qs[c * 64 + r] = g_kqv[(i0 + r) * N3 + DM + h * HD + c] * (1.0f / 32.0f);
    }

    float accv[64];
    #pragma unroll
    for (int d = 0; d < 64; ++d) accv[d] = 0.f;
    float m_run = -1e30f, l_run = 0.f;

    const int kt_hi = i0 >> 6;
    const int kt_lo = (kt_hi > 8) ? (kt_hi - 8) : 0;

    for (int kt = kt_lo; kt <= kt_hi; ++kt) {
        __syncthreads();   // prev PV done (and Q load on first iter)
        const int jb = kt * 64;
        for (int idx = tid; idx < 4096; idx += 256) {
            int r = idx >> 6, c = idx & 63;
            const float* src = &g_kqv[(jb + r) * N3 + h * HD + c];
            Ks[r * 64 + c] = src[0];
            Vs[r * 64 + c] = src[2048];
        }
        __syncthreads();

        // QK^T for this thread's 16 keys
        float s[16];
        #pragma unroll
        for (int kk = 0; kk < 16; ++kk) s[kk] = 0.f;
        #pragma unroll
        for (int d4 = 0; d4 < 16; ++d4) {
            float qv0 = Qs[(d4 * 4 + 0) * 64 + q];
            float qv1 = Qs[(d4 * 4 + 1) * 64 + q];
            float qv2 = Qs[(d4 * 4 + 2) * 64 + q];
            float qv3 = Qs[(d4 * 4 + 3) * 64 + q];
            #pragma unroll
            for (int kk = 0; kk < 16; ++kk) {
                float4 kv = *(const float4*)&Ks[(key0 + kk) * 64 + d4 * 4];
                s[kk] += qv0 * kv.x + qv1 * kv.y + qv2 * kv.z + qv3 * kv.w;
            }
        }
        // ALiBi bias + causal sliding-window mask: valid iff 0 <= i-j <= WIN
        #pragma unroll
        for (int kk = 0; kk < 16; ++kk) {
            int j = jb + key0 + kk;
            int dist = i - j;
            if (dist >= 0 && dist <= WIN) s[kk] -= slope * (float)dist;
            else                          s[kk] = -1e30f;
        }

        float mt = -1e30f;
        #pragma unroll
        for (int kk = 0; kk < 16; ++kk) mt = fmaxf(mt, s[kk]);
        redM[quad * 64 + q] = mt;
        __syncthreads();
        float m_new = m_run;
        #pragma unroll
        for (int p = 0; p < 4; ++p) m_new = fmaxf(m_new, redM[p * 64 + q]);

        float corr = __expf(m_run - m_new);
        float psum = 0.f;
        #pragma unroll
        for (int kk = 0; kk < 16; ++kk) { s[kk] = __expf(s[kk] - m_new); psum += s[kk]; }
        redL[quad * 64 + q] = psum;
        __syncthreads();
        float lsum = 0.f;
        #pragma unroll
        for (int p = 0; p < 4; ++p) lsum += redL[p * 64 + q];
        l_run = l_run * corr + lsum;
        m_run = m_new;

        #pragma unroll
        for (int d = 0; d < 64; ++d) accv[d] *= corr;

        // PV over this thread's 16 keys, all 64 dims (Vs reads warp-uniform)
        #pragma unroll
        for (int kk = 0; kk < 16; ++kk) {
            float p = s[kk];
            const float* vr = &Vs[(key0 + kk) * 64];
            #pragma unroll
            for (int d4 = 0; d4 < 16; ++d4) {
                float4 vv = *(const float4*)&vr[d4 * 4];
                accv[d4 * 4 + 0] += p * vv.x;
                accv[d4 * 4 + 1] += p * vv.y;
                accv[d4 * 4 + 2] += p * vv.z;
                accv[d4 * 4 + 3] += p * vv.w;
            }
        }
    }

    __syncthreads();
    // cross-quad reduction into Osum[q][65] (serialized by quad)
    for (int p = 0; p < 4; ++p) {
        if (quad == p) {
            if (p == 0) {
                redM[q] = 1.f / l_run;
                #pragma unroll
                for (int d = 0; d < 64; ++d) Osum[q * 65 + d] = accv[d];
            } else {
                #pragma unroll
                for (int d = 0; d < 64; ++d) Osum[q * 65 + d] += accv[d];
            }
        }
        __syncthreads();
    }

    for (int idx = tid; idx < 4096; idx += 256) {
        int r = idx >> 6, c = idx & 63;
        out[(i0 + r) * DM + h * HD + c] = Osum[r * 65 + c] * redM[r];
    }
}

// ---------------------------------------------------------------------------
extern "C" void kernel_launch(void* const* d_in, const int* in_sizes, int n_in,
                              void* d_out, int out_size) {
    const float* x = (const float*)d_in[0];    // [1, 4096, 1024]
    const float* w = (const float*)d_in[1];    // [1024, 3072]
    float* out = (float*)d_out;                // [1, 4096, 1024]

    gemm_kqv_kernel<<<dim3(N3 / 128, S_LEN / 128), 256>>>(x, w);

    const int attn_smem = 12800 * (int)sizeof(float);  // 51200 B
    cudaFuncSetAttribute(attn_alibi_kernel,
                         cudaFuncAttributeMaxDynamicSharedMemorySize, attn_smem);
    attn_alibi_kernel<<<dim3(S_LEN / 64, NHEADS), 256, attn_smem>>>(out);
}

// round 7
// speedup vs baseline: 1.3744x; 1.3744x over previous
#include <cuda_runtime.h>
#include <cuda_bf16.h>
#include <math.h>
#include <stdint.h>

#define S_LEN   4096
#define DM      1024
#define N3      3072
#define NHEADS  16
#define HD      64
#define WIN     512

// scratch: kqv = x @ w_kqv (fp32), cols 0..1023 = K, 1024..2047 = Q, 2048..3071 = V
__device__ float g_kqv[S_LEN * N3];
// bf16 hi/lo splits
__device__ __nv_bfloat16 g_Ah[S_LEN * DM];
__device__ __nv_bfloat16 g_Al[S_LEN * DM];
__device__ __nv_bfloat16 g_Bh[N3 * DM];   // transposed: [n][k]
__device__ __nv_bfloat16 g_Bl[N3 * DM];

// ---------------------------------------------------------------------------
// helpers
// ---------------------------------------------------------------------------
__device__ __forceinline__ uint32_t smem_u32(const void* p) {
    return (uint32_t)__cvta_generic_to_shared(p);
}

__device__ __forceinline__ void cp_async16(uint32_t dst, const void* src) {
    asm volatile("cp.async.cg.shared.global [%0], [%1], 16;" :: "r"(dst), "l"(src) : "memory");
}
#define CP_COMMIT() asm volatile("cp.async.commit_group;" ::: "memory")
#define CP_WAIT(n)  asm volatile("cp.async.wait_group %0;" :: "n"(n) : "memory")

#define LDM4(r0, r1, r2, r3, addr)                                            \
    asm volatile("ldmatrix.sync.aligned.m8n8.x4.shared.b16 {%0,%1,%2,%3}, [%4];" \
        : "=r"(r0), "=r"(r1), "=r"(r2), "=r"(r3) : "r"(addr))

#define MMA16816(d, a0, a1, a2, a3, b0, b1)                                   \
    asm volatile("mma.sync.aligned.m16n8k16.row.col.f32.bf16.bf16.f32 "       \
        "{%0,%1,%2,%3}, {%4,%5,%6,%7}, {%8,%9}, {%0,%1,%2,%3};"               \
        : "+f"((d)[0]), "+f"((d)[1]), "+f"((d)[2]), "+f"((d)[3])              \
        : "r"(a0), "r"(a1), "r"(a2), "r"(a3), "r"(b0), "r"(b1))

// ---------------------------------------------------------------------------
// Prep: split fp32 into bf16 hi + lo
// ---------------------------------------------------------------------------
__global__ void prep_x_kernel(const float* __restrict__ x) {
    int idx = blockIdx.x * 256 + threadIdx.x;
    float f = x[idx];
    __nv_bfloat16 hi = __float2bfloat16(f);
    g_Ah[idx] = hi;
    g_Al[idx] = __float2bfloat16(f - __bfloat162float(hi));
}

__global__ void prep_w_kernel(const float* __restrict__ w) {
    __shared__ float t[32][33];
    int n0 = blockIdx.x * 32, k0 = blockIdx.y * 32;
    int tx = threadIdx.x, ty = threadIdx.y;
    for (int r = ty; r < 32; r += 8)
        t[r][tx] = w[(size_t)(k0 + r) * N3 + n0 + tx];
    __syncthreads();
    for (int r = ty; r < 32; r += 8) {
        float f = t[tx][r];                       // w[k0+tx][n0+r]
        __nv_bfloat16 hi = __float2bfloat16(f);
        size_t o = (size_t)(n0 + r) * DM + k0 + tx;
        g_Bh[o] = hi;
        g_Bl[o] = __float2bfloat16(f - __bfloat162float(hi));
    }
}

// ---------------------------------------------------------------------------
// GEMM: C[4096,3072] = A @ W via bf16x3 mma.sync (hi*hi + hi*lo + lo*hi)
// 128x128 tile / CTA, 8 warps (64x32 each), K chunks of 64, cp.async double buf.
// smem rows padded to 72 bf16 (144 B) -> conflict-free ldmatrix.
// ---------------------------------------------------------------------------
#define LROW 72
#define ARR_B   (128 * LROW * 2)      // 18432 B per array
#define BUF_B   (4 * ARR_B)           // 73728 B per buffer

__global__ __launch_bounds__(256, 1)
void gemm_mma_kernel() {
    extern __shared__ char dsm[];
    const uint32_t sb = smem_u32(dsm);

    const int tid  = threadIdx.x;
    const int lane = tid & 31;
    const int w    = tid >> 5;
    const int m0   = blockIdx.y * 128;
    const int n0   = blockIdx.x * 128;
    const int wm   = (w >> 2) * 64;    // warp m offset in tile
    const int wn   = (w & 3) * 32;     // warp n offset in tile

    // per-thread cp.async source/dest mapping: unit u -> row=u>>3, 16B col unit u&7
    // issue one 64-col chunk for all four arrays
    auto issue = [&](int buf, int k0) {
        uint32_t base = sb + buf * BUF_B;
        #pragma unroll
        for (int it = 0; it < 4; ++it) {
            int u   = tid + it * 256;           // 0..1023
            int row = u >> 3;
            int c8  = (u & 7) * 8;
            uint32_t so = (uint32_t)(row * LROW + c8) * 2;
            cp_async16(base + 0 * ARR_B + so, &g_Ah[(size_t)(m0 + row) * DM + k0 + c8]);
            cp_async16(base + 1 * ARR_B + so, &g_Al[(size_t)(m0 + row) * DM + k0 + c8]);
            cp_async16(base + 2 * ARR_B + so, &g_Bh[(size_t)(n0 + row) * DM + k0 + c8]);
            cp_async16(base + 3 * ARR_B + so, &g_Bl[(size_t)(n0 + row) * DM + k0 + c8]);
        }
        CP_COMMIT();
    };

    float acc[4][4][4];
    #pragma unroll
    for (int i = 0; i < 4; ++i)
        #pragma unroll
        for (int j = 0; j < 4; ++j)
            #pragma unroll
            for (int r = 0; r < 4; ++r) acc[i][j][r] = 0.f;

    issue(0, 0);
    issue(1, 64);

    const int lrow = lane & 15;            // ldmatrix row within 16
    const int lk   = (lane >> 4) * 8;      // ldmatrix k sub-col

    for (int c = 0; c < 16; ++c) {
        if (c < 14) { CP_WAIT(1); } else { CP_WAIT(0); }
        __syncthreads();

        const uint32_t bufb = sb + (c & 1) * BUF_B;
        const uint32_t ahB = bufb + 0 * ARR_B;
        const uint32_t alB = bufb + 1 * ARR_B;
        const uint32_t bhB = bufb + 2 * ARR_B;
        const uint32_t blB = bufb + 3 * ARR_B;

        #pragma unroll
        for (int ks = 0; ks < 4; ++ks) {
            const int k0 = ks * 16;
            uint32_t ah[4][4], al[4][4], bh[2][4], bl[2][4];
            #pragma unroll
            for (int mt = 0; mt < 4; ++mt) {
                uint32_t off = (uint32_t)((wm + mt * 16 + lrow) * LROW + k0 + lk) * 2;
                LDM4(ah[mt][0], ah[mt][1], ah[mt][2], ah[mt][3], ahB + off);
                LDM4(al[mt][0], al[mt][1], al[mt][2], al[mt][3], alB + off);
            }
            #pragma unroll
            for (int nt2 = 0; nt2 < 2; ++nt2) {
                uint32_t off = (uint32_t)((wn + nt2 * 16 + lrow) * LROW + k0 + lk) * 2;
                LDM4(bh[nt2][0], bh[nt2][1], bh[nt2][2], bh[nt2][3], bhB + off);
                LDM4(bl[nt2][0], bl[nt2][1], bl[nt2][2], bl[nt2][3], blB + off);
            }
            // x4 B regs: ntile(nt2*2)   = {r0, r2};  ntile(nt2*2+1) = {r1, r3}
            #pragma unroll
            for (int mt = 0; mt < 4; ++mt) {
                #pragma unroll
                for (int nt2 = 0; nt2 < 2; ++nt2) {
                    // hi*hi
                    MMA16816(acc[mt][nt2 * 2 + 0], ah[mt][0], ah[mt][1], ah[mt][2], ah[mt][3],
                             bh[nt2][0], bh[nt2][2]);
                    MMA16816(acc[mt][nt2 * 2 + 1], ah[mt][0], ah[mt][1], ah[mt][2], ah[mt][3],
                             bh[nt2][1], bh[nt2][3]);
                    // hi*lo
                    MMA16816(acc[mt][nt2 * 2 + 0], ah[mt][0], ah[mt][1], ah[mt][2], ah[mt][3],
                             bl[nt2][0], bl[nt2][2]);
                    MMA16816(acc[mt][nt2 * 2 + 1], ah[mt][0], ah[mt][1], ah[mt][2], ah[mt][3],
                             bl[nt2][1], bl[nt2][3]);
                    // lo*hi
                    MMA16816(acc[mt][nt2 * 2 + 0], al[mt][0], al[mt][1], al[mt][2], al[mt][3],
                             bh[nt2][0], bh[nt2][2]);
                    MMA16816(acc[mt][nt2 * 2 + 1], al[mt][0], al[mt][1], al[mt][2], al[mt][3],
                             bh[nt2][1], bh[nt2][3]);
                }
            }
        }
        __syncthreads();
        if (c + 2 < 16) issue((c & 1), (c + 2) * 64);
    }

    // epilogue: acc frag -> g_kqv. c0,c1: row l/4, cols 2(l%4),+1; c2,c3: row l/4+8.
    const int er = lane >> 2;
    const int ec = (lane & 3) * 2;
    #pragma unroll
    for (int mt = 0; mt < 4; ++mt) {
        #pragma unroll
        for (int nt = 0; nt < 4; ++nt) {
            int row = m0 + wm + mt * 16 + er;
            int col = n0 + wn + nt * 8 + ec;
            *(float2*)&g_kqv[(size_t)row * N3 + col] =
                make_float2(acc[mt][nt][0], acc[mt][nt][1]);
            *(float2*)&g_kqv[(size_t)(row + 8) * N3 + col] =
                make_float2(acc[mt][nt][2], acc[mt][nt][3]);
        }
    }
}

// ---------------------------------------------------------------------------
// Kernel 2: sliding-window ALiBi attention with online softmax (unchanged).
// ---------------------------------------------------------------------------
__global__ __launch_bounds__(256, 2)
void attn_alibi_kernel(float* __restrict__ out) {
    extern __shared__ float sm[];
    float* Qs   = sm;            // [d][q]   64*64  (transposed)
    float* Ks   = sm + 4096;     // [key][d] 64*64
    float* Vs   = sm + 8192;     // [key][d] 64*64
    float* redM = sm + 12288;    // 256
    float* redL = sm + 12544;    // 256
    float* Osum = sm;            // overlay: [q][65]

    const int tid  = threadIdx.x;
    const int quad = tid >> 6;
    const int q    = tid & 63;
    const int key0 = quad * 16;
    const int i0   = blockIdx.x * 64;
    const int h    = blockIdx.y;
    const int i    = i0 + q;
    const float slope = exp2f(-0.5f * (float)(h + 1));

    for (int idx = tid; idx < 4096; idx += 256) {
        int r = idx >> 6, c = idx & 63;
        Qs[c * 64 + r] = g_kqv[(i0 + r) * N3 + DM + h * HD + c] * (1.0f / 32.0f);
    }

    float accv[64];
    #pragma unroll
    for (int d = 0; d < 64; ++d) accv[d] = 0.f;
    float m_run = -1e30f, l_run = 0.f;

    const int kt_hi = i0 >> 6;
    const int kt_lo = (kt_hi > 8) ? (kt_hi - 8) : 0;

    for (int kt = kt_lo; kt <= kt_hi; ++kt) {
        __syncthreads();
        const int jb = kt * 64;
        for (int idx = tid; idx < 4096; idx += 256) {
            int r = idx >> 6, c = idx & 63;
            const float* src = &g_kqv[(jb + r) * N3 + h * HD + c];
            Ks[r * 64 + c] = src[0];
            Vs[r * 64 + c] = src[2048];
        }
        __syncthreads();

        float s[16];
        #pragma unroll
        for (int kk = 0; kk < 16; ++kk) s[kk] = 0.f;
        #pragma unroll
        for (int d4 = 0; d4 < 16; ++d4) {
            float qv0 = Qs[(d4 * 4 + 0) * 64 + q];
            float qv1 = Qs[(d4 * 4 + 1) * 64 + q];
            float qv2 = Qs[(d4 * 4 + 2) * 64 + q];
            float qv3 = Qs[(d4 * 4 + 3) * 64 + q];
            #pragma unroll
            for (int kk = 0; kk < 16; ++kk) {
                float4 kv = *(const float4*)&Ks[(key0 + kk) * 64 + d4 * 4];
                s[kk] += qv0 * kv.x + qv1 * kv.y + qv2 * kv.z + qv3 * kv.w;
            }
        }
        #pragma unroll
        for (int kk = 0; kk < 16; ++kk) {
            int j = jb + key0 + kk;
            int dist = i - j;
            if (dist >= 0 && dist <= WIN) s[kk] -= slope * (float)dist;
            else                          s[kk] = -1e30f;
        }

        float mt = -1e30f;
        #pragma unroll
        for (int kk = 0; kk < 16; ++kk) mt = fmaxf(mt, s[kk]);
        redM[quad * 64 + q] = mt;
        __syncthreads();
        float m_new = m_run;
        #pragma unroll
        for (int p = 0; p < 4; ++p) m_new = fmaxf(m_new, redM[p * 64 + q]);

        float corr = __expf(m_run - m_new);
        float psum = 0.f;
        #pragma unroll
        for (int kk = 0; kk < 16; ++kk) { s[kk] = __expf(s[kk] - m_new); psum += s[kk]; }
        redL[quad * 64 + q] = psum;
        __syncthreads();
        float lsum = 0.f;
        #pragma unroll
        for (int p = 0; p < 4; ++p) lsum += redL[p * 64 + q];
        l_run = l_run * corr + lsum;
        m_run = m_new;

        #pragma unroll
        for (int d = 0; d < 64; ++d) accv[d] *= corr;

        #pragma unroll
        for (int kk = 0; kk < 16; ++kk) {
            float p = s[kk];
            const float* vr = &Vs[(key0 + kk) * 64];
            #pragma unroll
            for (int d4 = 0; d4 < 16; ++d4) {
                float4 vv = *(const float4*)&vr[d4 * 4];
                accv[d4 * 4 + 0] += p * vv.x;
                accv[d4 * 4 + 1] += p * vv.y;
                accv[d4 * 4 + 2] += p * vv.z;
                accv[d4 * 4 + 3] += p * vv.w;
            }
        }
    }

    __syncthreads();
    for (int p = 0; p < 4; ++p) {
        if (quad == p) {
            if (p == 0) {
                redM[q] = 1.f / l_run;
                #pragma unroll
                for (int d = 0; d < 64; ++d) Osum[q * 65 + d] = accv[d];
            } else {
                #pragma unroll
                for (int d = 0; d < 64; ++d) Osum[q * 65 + d] += accv[d];
            }
        }
        __syncthreads();
    }

    for (int idx = tid; idx < 4096; idx += 256) {
        int r = idx >> 6, c = idx & 63;
        out[(i0 + r) * DM + h * HD + c] = Osum[r * 65 + c] * redM[r];
    }
}

// ---------------------------------------------------------------------------
extern "C" void kernel_launch(void* const* d_in, const int* in_sizes, int n_in,
                              void* d_out, int out_size) {
    const float* x = (const float*)d_in[0];    // [1, 4096, 1024]
    const float* w = (const float*)d_in[1];    // [1024, 3072]
    float* out = (float*)d_out;                // [1, 4096, 1024]

    prep_x_kernel<<<S_LEN * DM / 256, 256>>>(x);
    prep_w_kernel<<<dim3(N3 / 32, DM / 32), dim3(32, 8)>>>(w);

    const int gemm_smem = 2 * BUF_B;           // 147456 B
    cudaFuncSetAttribute(gemm_mma_kernel,
                         cudaFuncAttributeMaxDynamicSharedMemorySize, gemm_smem);
    gemm_mma_kernel<<<dim3(N3 / 128, S_LEN / 128), 256, gemm_smem>>>();

    const int attn_smem = 12800 * (int)sizeof(float);  // 51200 B
    cudaFuncSetAttribute(attn_alibi_kernel,
                         cudaFuncAttributeMaxDynamicSharedMemorySize, attn_smem);
    attn_alibi_kernel<<<dim3(S_LEN / 64, NHEADS), 256, attn_smem>>>(out);
}

// round 12
// speedup vs baseline: 2.2073x; 1.6060x over previous
#include <cuda_runtime.h>
#include <cuda_bf16.h>
#include <math.h>
#include <stdint.h>

#define S_LEN   4096
#define DM      1024
#define N3      3072
#define NHEADS  16
#define HD      64
#define WIN     512

// bf16 hi/lo splits of GEMM inputs
__device__ __nv_bfloat16 g_Ah[S_LEN * DM];
__device__ __nv_bfloat16 g_Al[S_LEN * DM];
__device__ __nv_bfloat16 g_Bh[N3 * DM];   // transposed: [n][k]
__device__ __nv_bfloat16 g_Bl[N3 * DM];
// bf16 hi/lo of kqv = x @ w_kqv  (cols 0..1023 K, 1024..2047 Q, 2048..3071 V)
__device__ __nv_bfloat16 g_Ch[S_LEN * N3];
__device__ __nv_bfloat16 g_Cl[S_LEN * N3];

// ---------------------------------------------------------------------------
// helpers
// ---------------------------------------------------------------------------
__device__ __forceinline__ uint32_t smem_u32(const void* p) {
    return (uint32_t)__cvta_generic_to_shared(p);
}

__device__ __forceinline__ void cp_async16(uint32_t dst, const void* src) {
    asm volatile("cp.async.cg.shared.global [%0], [%1], 16;" :: "r"(dst), "l"(src) : "memory");
}
#define CP_COMMIT() asm volatile("cp.async.commit_group;" ::: "memory")
#define CP_WAIT(n)  asm volatile("cp.async.wait_group %0;" :: "n"(n) : "memory")

#define LDM4(r0, r1, r2, r3, addr)                                            \
    asm volatile("ldmatrix.sync.aligned.m8n8.x4.shared.b16 {%0,%1,%2,%3}, [%4];" \
        : "=r"(r0), "=r"(r1), "=r"(r2), "=r"(r3) : "r"(addr))

#define LDM4T(r0, r1, r2, r3, addr)                                           \
    asm volatile("ldmatrix.sync.aligned.m8n8.x4.trans.shared.b16 {%0,%1,%2,%3}, [%4];" \
        : "=r"(r0), "=r"(r1), "=r"(r2), "=r"(r3) : "r"(addr))

#define MMA16816(d, a0, a1, a2, a3, b0, b1)                                   \
    asm volatile("mma.sync.aligned.m16n8k16.row.col.f32.bf16.bf16.f32 "       \
        "{%0,%1,%2,%3}, {%4,%5,%6,%7}, {%8,%9}, {%0,%1,%2,%3};"               \
        : "+f"((d)[0]), "+f"((d)[1]), "+f"((d)[2]), "+f"((d)[3])              \
        : "r"(a0), "r"(a1), "r"(a2), "r"(a3), "r"(b0), "r"(b1))

// fast 2^t for t <= 0 (FFMA/ALU only; no MUFU). rel err ~6e-6.
__device__ __forceinline__ float fexp2(float t) {
    t = fmaxf(t, -125.0f);
    float fi = floorf(t);
    float f = t - fi;
    float p = 0.00015404f;
    p = fmaf(p, f, 0.00133336f);
    p = fmaf(p, f, 0.00961813f);
    p = fmaf(p, f, 0.05550411f);
    p = fmaf(p, f, 0.24022651f);
    p = fmaf(p, f, 0.69314718f);
    p = fmaf(p, f, 1.0f);
    return __int_as_float(__float_as_int(p) + (__float2int_rn(fi) << 23));
}

__device__ __forceinline__ uint32_t pack_bf16x2(float lo, float hi) {
    __nv_bfloat162 v = __halves2bfloat162(__float2bfloat16(lo), __float2bfloat16(hi));
    return *(uint32_t*)&v;
}

// ---------------------------------------------------------------------------
// Prep: split fp32 into bf16 hi + lo
// ---------------------------------------------------------------------------
__global__ void prep_x_kernel(const float* __restrict__ x) {
    int idx = blockIdx.x * 256 + threadIdx.x;
    float f = x[idx];
    __nv_bfloat16 hi = __float2bfloat16(f);
    g_Ah[idx] = hi;
    g_Al[idx] = __float2bfloat16(f - __bfloat162float(hi));
}

__global__ void prep_w_kernel(const float* __restrict__ w) {
    __shared__ float t[32][33];
    int n0 = blockIdx.x * 32, k0 = blockIdx.y * 32;
    int tx = threadIdx.x, ty = threadIdx.y;
    for (int r = ty; r < 32; r += 8)
        t[r][tx] = w[(size_t)(k0 + r) * N3 + n0 + tx];
    __syncthreads();
    for (int r = ty; r < 32; r += 8) {
        float f = t[tx][r];                       // w[k0+tx][n0+r]
        __nv_bfloat16 hi = __float2bfloat16(f);
        size_t o = (size_t)(n0 + r) * DM + k0 + tx;
        g_Bh[o] = hi;
        g_Bl[o] = __float2bfloat16(f - __bfloat162float(hi));
    }
}

// ---------------------------------------------------------------------------
// GEMM: kqv = A @ W via bf16x3 mma.sync. Epilogue writes bf16 hi/lo (g_Ch/g_Cl).
// ---------------------------------------------------------------------------
#define LROW 72
#define ARR_B   (128 * LROW * 2)      // 18432 B per array
#define BUF_B   (4 * ARR_B)           // 73728 B per buffer

__global__ __launch_bounds__(256, 1)
void gemm_mma_kernel() {
    extern __shared__ char dsm[];
    const uint32_t sb = smem_u32(dsm);

    const int tid  = threadIdx.x;
    const int lane = tid & 31;
    const int w    = tid >> 5;
    const int m0   = blockIdx.y * 128;
    const int n0   = blockIdx.x * 128;
    const int wm   = (w >> 2) * 64;
    const int wn   = (w & 3) * 32;

    auto issue = [&](int buf, int k0) {
        uint32_t base = sb + buf * BUF_B;
        #pragma unroll
        for (int it = 0; it < 4; ++it) {
            int u   = tid + it * 256;
            int row = u >> 3;
            int c8  = (u & 7) * 8;
            uint32_t so = (uint32_t)(row * LROW + c8) * 2;
            cp_async16(base + 0 * ARR_B + so, &g_Ah[(size_t)(m0 + row) * DM + k0 + c8]);
            cp_async16(base + 1 * ARR_B + so, &g_Al[(size_t)(m0 + row) * DM + k0 + c8]);
            cp_async16(base + 2 * ARR_B + so, &g_Bh[(size_t)(n0 + row) * DM + k0 + c8]);
            cp_async16(base + 3 * ARR_B + so, &g_Bl[(size_t)(n0 + row) * DM + k0 + c8]);
        }
        CP_COMMIT();
    };

    float acc[4][4][4];
    #pragma unroll
    for (int i = 0; i < 4; ++i)
        #pragma unroll
        for (int j = 0; j < 4; ++j)
            #pragma unroll
            for (int r = 0; r < 4; ++r) acc[i][j][r] = 0.f;

    issue(0, 0);
    issue(1, 64);

    const int lrow = lane & 15;
    const int lk   = (lane >> 4) * 8;

    for (int c = 0; c < 16; ++c) {
        if (c < 14) { CP_WAIT(1); } else { CP_WAIT(0); }
        __syncthreads();

        const uint32_t bufb = sb + (c & 1) * BUF_B;
        const uint32_t ahB = bufb + 0 * ARR_B;
        const uint32_t alB = bufb + 1 * ARR_B;
        const uint32_t bhB = bufb + 2 * ARR_B;
        const uint32_t blB = bufb + 3 * ARR_B;

        #pragma unroll
        for (int ks = 0; ks < 4; ++ks) {
            const int k0 = ks * 16;
            uint32_t ah[4][4], al[4][4], bh[2][4], bl[2][4];
            #pragma unroll
            for (int mt = 0; mt < 4; ++mt) {
                uint32_t off = (uint32_t)((wm + mt * 16 + lrow) * LROW + k0 + lk) * 2;
                LDM4(ah[mt][0], ah[mt][1], ah[mt][2], ah[mt][3], ahB + off);
                LDM4(al[mt][0], al[mt][1], al[mt][2], al[mt][3], alB + off);
            }
            #pragma unroll
            for (int nt2 = 0; nt2 < 2; ++nt2) {
                uint32_t off = (uint32_t)((wn + nt2 * 16 + lrow) * LROW + k0 + lk) * 2;
                LDM4(bh[nt2][0], bh[nt2][1], bh[nt2][2], bh[nt2][3], bhB + off);
                LDM4(bl[nt2][0], bl[nt2][1], bl[nt2][2], bl[nt2][3], blB + off);
            }
            #pragma unroll
            for (int mt = 0; mt < 4; ++mt) {
                #pragma unroll
                for (int nt2 = 0; nt2 < 2; ++nt2) {
                    MMA16816(acc[mt][nt2 * 2 + 0], ah[mt][0], ah[mt][1], ah[mt][2], ah[mt][3],
                             bh[nt2][0], bh[nt2][2]);
                    MMA16816(acc[mt][nt2 * 2 + 1], ah[mt][0], ah[mt][1], ah[mt][2], ah[mt][3],
                             bh[nt2][1], bh[nt2][3]);
                    MMA16816(acc[mt][nt2 * 2 + 0], ah[mt][0], ah[mt][1], ah[mt][2], ah[mt][3],
                             bl[nt2][0], bl[nt2][2]);
                    MMA16816(acc[mt][nt2 * 2 + 1], ah[mt][0], ah[mt][1], ah[mt][2], ah[mt][3],
                             bl[nt2][1], bl[nt2][3]);
                    MMA16816(acc[mt][nt2 * 2 + 0], al[mt][0], al[mt][1], al[mt][2], al[mt][3],
                             bh[nt2][0], bh[nt2][2]);
                    MMA16816(acc[mt][nt2 * 2 + 1], al[mt][0], al[mt][1], al[mt][2], al[mt][3],
                             bh[nt2][1], bh[nt2][3]);
                }
            }
        }
        __syncthreads();
        if (c + 2 < 16) issue((c & 1), (c + 2) * 64);
    }

    // epilogue: fp32 acc -> bf16 hi/lo
    const int er = lane >> 2;
    const int ec = (lane & 3) * 2;
    #pragma unroll
    for (int mt = 0; mt < 4; ++mt) {
        #pragma unroll
        for (int nt = 0; nt < 4; ++nt) {
            int row = m0 + wm + mt * 16 + er;
            int col = n0 + wn + nt * 8 + ec;
            #pragma unroll
            for (int half = 0; half < 2; ++half) {
                float x0 = acc[mt][nt][half * 2 + 0];
                float x1 = acc[mt][nt][half * 2 + 1];
                __nv_bfloat16 h0 = __float2bfloat16(x0);
                __nv_bfloat16 h1 = __float2bfloat16(x1);
                __nv_bfloat16 l0 = __float2bfloat16(x0 - __bfloat162float(h0));
                __nv_bfloat16 l1 = __float2bfloat16(x1 - __bfloat162float(h1));
                size_t o = (size_t)(row + half * 8) * N3 + col;
                *(__nv_bfloat162*)&g_Ch[o] = __halves2bfloat162(h0, h1);
                *(__nv_bfloat162*)&g_Cl[o] = __halves2bfloat162(l0, l1);
            }
        }
    }
}

// ---------------------------------------------------------------------------
// Attention: FA2-style mma.sync, bf16x3 QK and PV, FFMA softmax (base-2).
// CTA = (128 q-rows, head). 8 warps x 16 q-rows. Key tiles of 64, dbl-buffered.
// ---------------------------------------------------------------------------
#define BQ 128
#define BK 64
#define KVTILE_B (BK * LROW * 2)     // 9216 B per array

__global__ __launch_bounds__(256, 1)
void attn_mma_kernel(float* __restrict__ out) {
    extern __shared__ char sm[];
    const uint32_t sb  = smem_u32(sm);
    const uint32_t QH  = sb;
    const uint32_t QL  = sb + BQ * LROW * 2;
    const uint32_t KV0 = sb + 2 * BQ * LROW * 2;   // stage s: KV0 + s*4*KVTILE_B

    const int tid  = threadIdx.x;
    const int lane = tid & 31;
    const int w    = tid >> 5;
    const int wq   = w * 16;
    const int h    = blockIdx.y;
    const int q0   = blockIdx.x * BQ;
    const float slope2 = exp2f(-0.5f * (float)(h + 1)) * 1.44269504f;
    const float C1     = 1.44269504f / 32.0f;

    // Q load (both hi and lo): 2048 x 16B chunks
    #pragma unroll
    for (int k = 0; k < 8; ++k) {
        int cid = tid + 256 * k;
        int arr = cid >> 10;                 // 0: hi, 1: lo
        int r   = (cid >> 3) & 127;
        int c8  = (cid & 7) * 8;
        const __nv_bfloat16* src =
            (arr ? g_Cl : g_Ch) + (size_t)(q0 + r) * N3 + DM + h * HD + c8;
        cp_async16((arr ? QL : QH) + (uint32_t)(r * LROW + c8) * 2, src);
    }

    const int kt_lo = max(0, (q0 >> 6) - 8);
    const int kt_hi = (q0 >> 6) + 1;
    const int nkt   = kt_hi - kt_lo + 1;

    auto issueKV = [&](int idx) {
        int jb = (kt_lo + idx) * BK;
        uint32_t base = KV0 + (idx & 1) * 4 * KVTILE_B;
        #pragma unroll
        for (int k = 0; k < 8; ++k) {
            int cid = tid + 256 * k;
            int arr = cid >> 9;              // 0:Kh 1:Kl 2:Vh 3:Vl
            int r   = (cid >> 3) & 63;
            int c8  = (cid & 7) * 8;
            const __nv_bfloat16* g = (arr & 1) ? g_Cl : g_Ch;
            int colbase = ((arr >> 1) ? 2 * DM : 0) + h * HD;
            cp_async16(base + arr * KVTILE_B + (uint32_t)(r * LROW + c8) * 2,
                       g + (size_t)(jb + r) * N3 + colbase + c8);
        }
        CP_COMMIT();
    };

    issueKV(0);
    if (nkt > 1) issueKV(1);

    float o[8][4];
    #pragma unroll
    for (int i = 0; i < 8; ++i)
        #pragma unroll
        for (int j = 0; j < 4; ++j) o[i][j] = 0.f;
    float m_run0 = -1e30f, m_run1 = -1e30f;
    float l_run0 = 0.f, l_run1 = 0.f;

    const int r0g   = q0 + wq + (lane >> 2);       // global i for frag row 0
    const int lrow  = lane & 15;
    const int lk    = (lane >> 4) * 8;

    for (int it = 0; it < nkt; ++it) {
        if (it + 1 < nkt) { CP_WAIT(1); } else { CP_WAIT(0); }
        __syncthreads();
        const uint32_t kb  = KV0 + (it & 1) * 4 * KVTILE_B;
        const uint32_t KHb = kb, KLb = kb + KVTILE_B;
        const uint32_t VHb = kb + 2 * KVTILE_B, VLb = kb + 3 * KVTILE_B;
        const int jb = (kt_lo + it) * BK;

        // ---- QK^T (bf16 3-term) ----
        float sc[8][4];
        #pragma unroll
        for (int i = 0; i < 8; ++i)
            #pragma unroll
            for (int j = 0; j < 4; ++j) sc[i][j] = 0.f;

        #pragma unroll
        for (int ks = 0; ks < 4; ++ks) {
            uint32_t qh[4], ql[4];
            uint32_t qoff = (uint32_t)((wq + lrow) * LROW + ks * 16 + lk) * 2;
            LDM4(qh[0], qh[1], qh[2], qh[3], QH + qoff);
            LDM4(ql[0], ql[1], ql[2], ql[3], QL + qoff);
            #pragma unroll
            for (int np = 0; np < 4; ++np) {
                uint32_t bh[4], bl[4];
                uint32_t koff = (uint32_t)((np * 16 + lrow) * LROW + ks * 16 + lk) * 2;
                LDM4(bh[0], bh[1], bh[2], bh[3], KHb + koff);
                LDM4(bl[0], bl[1], bl[2], bl[3], KLb + koff);
                MMA16816(sc[2 * np + 0], qh[0], qh[1], qh[2], qh[3], bh[0], bh[2]);
                MMA16816(sc[2 * np + 1], qh[0], qh[1], qh[2], qh[3], bh[1], bh[3]);
                MMA16816(sc[2 * np + 0], qh[0], qh[1], qh[2], qh[3], bl[0], bl[2]);
                MMA16816(sc[2 * np + 1], qh[0], qh[1], qh[2], qh[3], bl[1], bl[3]);
                MMA16816(sc[2 * np + 0], ql[0], ql[1], ql[2], ql[3], bh[0], bh[2]);
                MMA16816(sc[2 * np + 1], ql[0], ql[1], ql[2], ql[3], bh[1], bh[3]);
            }
        }

        // ---- bias + mask + online softmax (base-2, FFMA exp) ----
        const int jbase = jb + 2 * (lane & 3);
        float mloc0 = -1e30f, mloc1 = -1e30f;
        #pragma unroll
        for (int nt = 0; nt < 8; ++nt) {
            #pragma unroll
            for (int e = 0; e < 4; ++e) {
                int j  = jbase + nt * 8 + (e & 1);
                int i  = r0g + ((e >> 1) << 3);
                int jr = j - i;                      // valid iff -512 <= jr <= 0
                float t = fmaf(sc[nt][e], C1, slope2 * (float)jr);
                bool valid = (jr <= 0) && (jr >= -WIN);
                t = valid ? t : -1e30f;
                sc[nt][e] = t;
                if (e < 2) mloc0 = fmaxf(mloc0, t);
                else       mloc1 = fmaxf(mloc1, t);
            }
        }
        mloc0 = fmaxf(mloc0, __shfl_xor_sync(0xffffffffu, mloc0, 1));
        mloc0 = fmaxf(mloc0, __shfl_xor_sync(0xffffffffu, mloc0, 2));
        mloc1 = fmaxf(mloc1, __shfl_xor_sync(0xffffffffu, mloc1, 1));
        mloc1 = fmaxf(mloc1, __shfl_xor_sync(0xffffffffu, mloc1, 2));

        float m_new0 = fmaxf(m_run0, mloc0);
        float m_new1 = fmaxf(m_run1, mloc1);
        float corr0 = fexp2(m_run0 - m_new0);
        float corr1 = fexp2(m_run1 - m_new1);
        m_run0 = m_new0; m_run1 = m_new1;

        float ps0 = 0.f, ps1 = 0.f;
        #pragma unroll
        for (int nt = 0; nt < 8; ++nt) {
            float p0 = fexp2(sc[nt][0] - m_new0);
            float p1 = fexp2(sc[nt][1] - m_new0);
            float p2 = fexp2(sc[nt][2] - m_new1);
            float p3 = fexp2(sc[nt][3] - m_new1);
            sc[nt][0] = p0; sc[nt][1] = p1; sc[nt][2] = p2; sc[nt][3] = p3;
            ps0 += p0 + p1; ps1 += p2 + p3;
        }
        ps0 += __shfl_xor_sync(0xffffffffu, ps0, 1);
        ps0 += __shfl_xor_sync(0xffffffffu, ps0, 2);
        ps1 += __shfl_xor_sync(0xffffffffu, ps1, 1);
        ps1 += __shfl_xor_sync(0xffffffffu, ps1, 2);
        l_run0 = l_run0 * corr0 + ps0;
        l_run1 = l_run1 * corr1 + ps1;

        #pragma unroll
        for (int nt = 0; nt < 8; ++nt) {
            o[nt][0] *= corr0; o[nt][1] *= corr0;
            o[nt][2] *= corr1; o[nt][3] *= corr1;
        }

        // ---- PV (P hi/lo, V hi/lo, 3-term) ----
        #pragma unroll
        for (int ks = 0; ks < 4; ++ks) {
            // A frags from sc[2ks], sc[2ks+1] (C-frag layout == A-frag layout)
            float p00 = sc[2 * ks][0],     p01 = sc[2 * ks][1];
            float p02 = sc[2 * ks][2],     p03 = sc[2 * ks][3];
            float p10 = sc[2 * ks + 1][0], p11 = sc[2 * ks + 1][1];
            float p12 = sc[2 * ks + 1][2], p13 = sc[2 * ks + 1][3];
            uint32_t ph[4], pl[4];
            ph[0] = pack_bf16x2(p00, p01);
            ph[1] = pack_bf16x2(p02, p03);
            ph[2] = pack_bf16x2(p10, p11);
            ph[3] = pack_bf16x2(p12, p13);
            {
                __nv_bfloat162 h;
                h = *(__nv_bfloat162*)&ph[0];
                pl[0] = pack_bf16x2(p00 - __bfloat162float(h.x), p01 - __bfloat162float(h.y));
                h = *(__nv_bfloat162*)&ph[1];
                pl[1] = pack_bf16x2(p02 - __bfloat162float(h.x), p03 - __bfloat162float(h.y));
                h = *(__nv_bfloat162*)&ph[2];
                pl[2] = pack_bf16x2(p10 - __bfloat162float(h.x), p11 - __bfloat162float(h.y));
                h = *(__nv_bfloat162*)&ph[3];
                pl[3] = pack_bf16x2(p12 - __bfloat162float(h.x), p13 - __bfloat162float(h.y));
            }
            #pragma unroll
            for (int dp = 0; dp < 4; ++dp) {
                uint32_t vh[4], vl[4];
                uint32_t voff = (uint32_t)((ks * 16 + ((lane >> 3) & 1) * 8 + (lane & 7)) * LROW
                                           + dp * 16 + lk) * 2;
                LDM4T(vh[0], vh[1], vh[2], vh[3], VHb + voff);
                LDM4T(vl[0], vl[1], vl[2], vl[3], VLb + voff);
                MMA16816(o[2 * dp + 0], ph[0], ph[1], ph[2], ph[3], vh[0], vh[1]);
                MMA16816(o[2 * dp + 1], ph[0], ph[1], ph[2], ph[3], vh[2], vh[3]);
                MMA16816(o[2 * dp + 0], ph[0], ph[1], ph[2], ph[3], vl[0], vl[1]);
                MMA16816(o[2 * dp + 1], ph[0], ph[1], ph[2], ph[3], vl[2], vl[3]);
                MMA16816(o[2 * dp + 0], pl[0], pl[1], pl[2], pl[3], vh[0], vh[1]);
                MMA16816(o[2 * dp + 1], pl[0], pl[1], pl[2], pl[3], vh[2], vh[3]);
            }
        }

        __syncthreads();
        if (it + 2 < nkt) issueKV(it + 2);
    }

    // ---- write out ----
    float inv0 = 1.f / l_run0;
    float inv1 = 1.f / l_run1;
    const int cb = h * HD + 2 * (lane & 3);
    #pragma unroll
    for (int nt = 0; nt < 8; ++nt) {
        *(float2*)&out[(size_t)r0g * DM + cb + nt * 8] =
            make_float2(o[nt][0] * inv0, o[nt][1] * inv0);
        *(float2*)&out[(size_t)(r0g + 8) * DM + cb + nt * 8] =
            make_float2(o[nt][2] * inv1, o[nt][3] * inv1);
    }
}

// ---------------------------------------------------------------------------
extern "C" void kernel_launch(void* const* d_in, const int* in_sizes, int n_in,
                              void* d_out, int out_size) {
    const float* x = (const float*)d_in[0];    // [1, 4096, 1024]
    const float* w = (const float*)d_in[1];    // [1024, 3072]
    float* out = (float*)d_out;                // [1, 4096, 1024]

    prep_x_kernel<<<S_LEN * DM / 256, 256>>>(x);
    prep_w_kernel<<<dim3(N3 / 32, DM / 32), dim3(32, 8)>>>(w);

    const int gemm_smem = 2 * BUF_B;           // 147456 B
    cudaFuncSetAttribute(gemm_mma_kernel,
                         cudaFuncAttributeMaxDynamicSharedMemorySize, gemm_smem);
    gemm_mma_kernel<<<dim3(N3 / 128, S_LEN / 128), 256, gemm_smem>>>();

    const int attn_smem = 2 * BQ * LROW * 2 + 2 * 4 * KVTILE_B;   // 110592 B
    cudaFuncSetAttribute(attn_mma_kernel,
                         cudaFuncAttributeMaxDynamicSharedMemorySize, attn_smem);
    attn_mma_kernel<<<dim3(S_LEN / BQ, NHEADS), 256, attn_smem>>>(out);
}

// round 16
// speedup vs baseline: 3.7843x; 1.7145x over previous
#include <cuda_runtime.h>
#include <cuda_fp16.h>
#include <math.h>
#include <stdint.h>

#define S_LEN   4096
#define DM      1024
#define N3      3072
#define NHEADS  16
#define HD      64
#define WIN     512

// fp16 hi/lo of x, fp16 hi of w^T
__device__ __half g_Xh[S_LEN * DM];
__device__ __half g_Xl[S_LEN * DM];
__device__ __half g_Wh[N3 * DM];          // transposed: [n][k]
// fp16 kqv = x @ w_kqv  (cols 0..1023 K, 1024..2047 Q, 2048..3071 V)
__device__ __half g_C[S_LEN * N3];

// ---------------------------------------------------------------------------
// helpers
// ---------------------------------------------------------------------------
__device__ __forceinline__ uint32_t smem_u32(const void* p) {
    return (uint32_t)__cvta_generic_to_shared(p);
}

__device__ __forceinline__ void cp_async16(uint32_t dst, const void* src) {
    asm volatile("cp.async.cg.shared.global [%0], [%1], 16;" :: "r"(dst), "l"(src) : "memory");
}
#define CP_COMMIT() asm volatile("cp.async.commit_group;" ::: "memory")
#define CP_WAIT(n)  asm volatile("cp.async.wait_group %0;" :: "n"(n) : "memory")

#define LDM4(r0, r1, r2, r3, addr)                                            \
    asm volatile("ldmatrix.sync.aligned.m8n8.x4.shared.b16 {%0,%1,%2,%3}, [%4];" \
        : "=r"(r0), "=r"(r1), "=r"(r2), "=r"(r3) : "r"(addr))

#define LDM4T(r0, r1, r2, r3, addr)                                           \
    asm volatile("ldmatrix.sync.aligned.m8n8.x4.trans.shared.b16 {%0,%1,%2,%3}, [%4];" \
        : "=r"(r0), "=r"(r1), "=r"(r2), "=r"(r3) : "r"(addr))

#define MMA16816(d, a0, a1, a2, a3, b0, b1)                                   \
    asm volatile("mma.sync.aligned.m16n8k16.row.col.f32.f16.f16.f32 "         \
        "{%0,%1,%2,%3}, {%4,%5,%6,%7}, {%8,%9}, {%0,%1,%2,%3};"               \
        : "+f"((d)[0]), "+f"((d)[1]), "+f"((d)[2]), "+f"((d)[3])              \
        : "r"(a0), "r"(a1), "r"(a2), "r"(a3), "r"(b0), "r"(b1))

// hardware 2^x (MUFU.EX2); ftz flushes the -1e30 case to 0.
__device__ __forceinline__ float ex2(float x) {
    float r;
    asm("ex2.approx.ftz.f32 %0, %1;" : "=f"(r) : "f"(x));
    return r;
}

__device__ __forceinline__ uint32_t pack_h2(float a, float b) {
    __half2 h = __floats2half2_rn(a, b);
    return *(uint32_t*)&h;
}

// ---------------------------------------------------------------------------
// Prep
// ---------------------------------------------------------------------------
__global__ void prep_x_kernel(const float* __restrict__ x) {
    int idx = blockIdx.x * 256 + threadIdx.x;
    float f = x[idx];
    __half hi = __float2half_rn(f);
    g_Xh[idx] = hi;
    g_Xl[idx] = __float2half_rn(f - __half2float(hi));
}

__global__ void prep_w_kernel(const float* __restrict__ w) {
    __shared__ float t[32][33];
    int n0 = blockIdx.x * 32, k0 = blockIdx.y * 32;
    int tx = threadIdx.x, ty = threadIdx.y;
    for (int r = ty; r < 32; r += 8)
        t[r][tx] = w[(size_t)(k0 + r) * N3 + n0 + tx];
    __syncthreads();
    for (int r = ty; r < 32; r += 8)
        g_Wh[(size_t)(n0 + r) * DM + k0 + tx] = __float2half_rn(t[tx][r]);
}

// ---------------------------------------------------------------------------
// GEMM: C = X @ W via fp16 2-term mma.sync (XhWh + XlWh), fp32 accum.
// 128x128 tile / CTA, 8 warps (64x32), K chunks of 64, cp.async double buffer.
// ---------------------------------------------------------------------------
#define LROW 72
#define ARR_B   (128 * LROW * 2)      // 18432 B per array
#define BUF_B   (3 * ARR_B)           // 55296 B per buffer (Xh, Xl, Wh)

__global__ __launch_bounds__(256, 2)
void gemm_mma_kernel() {
    extern __shared__ char dsm[];
    const uint32_t sb = smem_u32(dsm);

    const int tid  = threadIdx.x;
    const int lane = tid & 31;
    const int w    = tid >> 5;
    const int m0   = blockIdx.y * 128;
    const int n0   = blockIdx.x * 128;
    const int wm   = (w >> 2) * 64;
    const int wn   = (w & 3) * 32;

    auto issue = [&](int buf, int k0) {
        uint32_t base = sb + buf * BUF_B;
        #pragma unroll
        for (int it = 0; it < 12; ++it) {
            int cid = tid + it * 256;            // 0..3071
            int arr = cid >> 10;                 // 0:Xh 1:Xl 2:Wh
            int row = (cid >> 3) & 127;
            int c8  = (cid & 7) * 8;
            uint32_t so = base + arr * ARR_B + (uint32_t)(row * LROW + c8) * 2;
            const __half* src = (arr == 0) ? &g_Xh[(size_t)(m0 + row) * DM + k0 + c8]
                              : (arr == 1) ? &g_Xl[(size_t)(m0 + row) * DM + k0 + c8]
                                           : &g_Wh[(size_t)(n0 + row) * DM + k0 + c8];
            cp_async16(so, src);
        }
        CP_COMMIT();
    };

    float acc[4][4][4];
    #pragma unroll
    for (int i = 0; i < 4; ++i)
        #pragma unroll
        for (int j = 0; j < 4; ++j)
            #pragma unroll
            for (int r = 0; r < 4; ++r) acc[i][j][r] = 0.f;

    issue(0, 0);
    issue(1, 64);

    const int lrow = lane & 15;
    const int lk   = (lane >> 4) * 8;

    for (int c = 0; c < 16; ++c) {
        if (c < 14) { CP_WAIT(1); } else { CP_WAIT(0); }
        __syncthreads();

        const uint32_t bufb = sb + (c & 1) * BUF_B;
        const uint32_t xhB = bufb;
        const uint32_t xlB = bufb + ARR_B;
        const uint32_t whB = bufb + 2 * ARR_B;

        #pragma unroll
        for (int ks = 0; ks < 4; ++ks) {
            const int k0 = ks * 16;
            uint32_t ah[4][4], al[4][4], bh[2][4];
            #pragma unroll
            for (int mt = 0; mt < 4; ++mt) {
                uint32_t off = (uint32_t)((wm + mt * 16 + lrow) * LROW + k0 + lk) * 2;
                LDM4(ah[mt][0], ah[mt][1], ah[mt][2], ah[mt][3], xhB + off);
                LDM4(al[mt][0], al[mt][1], al[mt][2], al[mt][3], xlB + off);
            }
            #pragma unroll
            for (int nt2 = 0; nt2 < 2; ++nt2) {
                uint32_t off = (uint32_t)((wn + nt2 * 16 + lrow) * LROW + k0 + lk) * 2;
                LDM4(bh[nt2][0], bh[nt2][1], bh[nt2][2], bh[nt2][3], whB + off);
            }
            #pragma unroll
            for (int mt = 0; mt < 4; ++mt) {
                #pragma unroll
                for (int nt2 = 0; nt2 < 2; ++nt2) {
                    MMA16816(acc[mt][nt2 * 2 + 0], ah[mt][0], ah[mt][1], ah[mt][2], ah[mt][3],
                             bh[nt2][0], bh[nt2][2]);
                    MMA16816(acc[mt][nt2 * 2 + 1], ah[mt][0], ah[mt][1], ah[mt][2], ah[mt][3],
                             bh[nt2][1], bh[nt2][3]);
                    MMA16816(acc[mt][nt2 * 2 + 0], al[mt][0], al[mt][1], al[mt][2], al[mt][3],
                             bh[nt2][0], bh[nt2][2]);
                    MMA16816(acc[mt][nt2 * 2 + 1], al[mt][0], al[mt][1], al[mt][2], al[mt][3],
                             bh[nt2][1], bh[nt2][3]);
                }
            }
        }
        __syncthreads();
        if (c + 2 < 16) issue((c & 1), (c + 2) * 64);
    }

    // epilogue: fp32 acc -> fp16 C
    const int er = lane >> 2;
    const int ec = (lane & 3) * 2;
    #pragma unroll
    for (int mt = 0; mt < 4; ++mt) {
        #pragma unroll
        for (int nt = 0; nt < 4; ++nt) {
            int row = m0 + wm + mt * 16 + er;
            int col = n0 + wn + nt * 8 + ec;
            __half2 v01 = __floats2half2_rn(acc[mt][nt][0], acc[mt][nt][1]);
            __half2 v23 = __floats2half2_rn(acc[mt][nt][2], acc[mt][nt][3]);
            *(__half2*)&g_C[(size_t)row * N3 + col] = v01;
            *(__half2*)&g_C[(size_t)(row + 8) * N3 + col] = v23;
        }
    }
}

// ---------------------------------------------------------------------------
// Attention: FA2-style fp16 mma.sync, 1-term QK and PV, MUFU softmax (base-2).
// CTA = (128 q-rows, head). 8 warps x 16 q-rows. Key tiles of 64, dbl-buffered.
// ---------------------------------------------------------------------------
#define BQ 128
#define BK 64
#define KVTILE_B (BK * LROW * 2)     // 9216 B per array (Kh, Vh)

__global__ __launch_bounds__(256, 2)
void attn_mma_kernel(float* __restrict__ out) {
    extern __shared__ char sm[];
    const uint32_t sb  = smem_u32(sm);
    const uint32_t QHb = sb;
    const uint32_t KV0 = sb + BQ * LROW * 2;       // stage s: KV0 + s*2*KVTILE_B

    const int tid  = threadIdx.x;
    const int lane = tid & 31;
    const int w    = tid >> 5;
    const int wq   = w * 16;
    const int h    = blockIdx.y;
    const int q0   = blockIdx.x * BQ;
    const float slope2 = exp2f(-0.5f * (float)(h + 1)) * 1.44269504f;
    const float C1     = 1.44269504f / 32.0f;

    // Q hi load: 1024 x 16B chunks
    #pragma unroll
    for (int k = 0; k < 4; ++k) {
        int cid = tid + 256 * k;
        int r   = cid >> 3;
        int c8  = (cid & 7) * 8;
        cp_async16(QHb + (uint32_t)(r * LROW + c8) * 2,
                   &g_C[(size_t)(q0 + r) * N3 + DM + h * HD + c8]);
    }

    const int kt_lo = max(0, (q0 >> 6) - 8);
    const int kt_hi = (q0 >> 6) + 1;
    const int nkt   = kt_hi - kt_lo + 1;

    auto issueKV = [&](int idx) {
        int jb = (kt_lo + idx) * BK;
        uint32_t base = KV0 + (idx & 1) * 2 * KVTILE_B;
        #pragma unroll
        for (int k = 0; k < 4; ++k) {
            int cid = tid + 256 * k;
            int arr = cid >> 9;                  // 0:Kh 1:Vh
            int r   = (cid >> 3) & 63;
            int c8  = (cid & 7) * 8;
            int colbase = (arr ? 2 * DM : 0) + h * HD;
            cp_async16(base + arr * KVTILE_B + (uint32_t)(r * LROW + c8) * 2,
                       &g_C[(size_t)(jb + r) * N3 + colbase + c8]);
        }
        CP_COMMIT();
    };

    issueKV(0);
    if (nkt > 1) issueKV(1);

    float o[8][4];
    #pragma unroll
    for (int i = 0; i < 8; ++i)
        #pragma unroll
        for (int j = 0; j < 4; ++j) o[i][j] = 0.f;
    float m_run0 = -1e30f, m_run1 = -1e30f;
    float l_run0 = 0.f, l_run1 = 0.f;

    const int r0g   = q0 + wq + (lane >> 2);
    const int lrow  = lane & 15;
    const int lk    = (lane >> 4) * 8;

    for (int it = 0; it < nkt; ++it) {
        if (it + 1 < nkt) { CP_WAIT(1); } else { CP_WAIT(0); }
        __syncthreads();
        const uint32_t kb  = KV0 + (it & 1) * 2 * KVTILE_B;
        const uint32_t KHb = kb, VHb = kb + KVTILE_B;
        const int jb = (kt_lo + it) * BK;

        // ---- QK^T (1 term) ----
        float sc[8][4];
        #pragma unroll
        for (int i = 0; i < 8; ++i)
            #pragma unroll
            for (int j = 0; j < 4; ++j) sc[i][j] = 0.f;

        #pragma unroll
        for (int ks = 0; ks < 4; ++ks) {
            uint32_t qh[4];
            uint32_t qoff = (uint32_t)((wq + lrow) * LROW + ks * 16 + lk) * 2;
            LDM4(qh[0], qh[1], qh[2], qh[3], QHb + qoff);
            #pragma unroll
            for (int np = 0; np < 4; ++np) {
                uint32_t bh[4];
                uint32_t koff = (uint32_t)((np * 16 + lrow) * LROW + ks * 16 + lk) * 2;
                LDM4(bh[0], bh[1], bh[2], bh[3], KHb + koff);
                MMA16816(sc[2 * np + 0], qh[0], qh[1], qh[2], qh[3], bh[0], bh[2]);
                MMA16816(sc[2 * np + 1], qh[0], qh[1], qh[2], qh[3], bh[1], bh[3]);
            }
        }

        // ---- bias + mask + online softmax (base-2, MUFU ex2) ----
        const int jbase = jb + 2 * (lane & 3);
        float mloc0 = -1e30f, mloc1 = -1e30f;
        #pragma unroll
        for (int nt = 0; nt < 8; ++nt) {
            #pragma unroll
            for (int e = 0; e < 4; ++e) {
                int j  = jbase + nt * 8 + (e & 1);
                int i  = r0g + ((e >> 1) << 3);
                int jr = j - i;                      // valid iff -512 <= jr <= 0
                float t = fmaf(sc[nt][e], C1, slope2 * (float)jr);
                bool valid = (jr <= 0) && (jr >= -WIN);
                t = valid ? t : -1e30f;
                sc[nt][e] = t;
                if (e < 2) mloc0 = fmaxf(mloc0, t);
                else       mloc1 = fmaxf(mloc1, t);
            }
        }
        mloc0 = fmaxf(mloc0, __shfl_xor_sync(0xffffffffu, mloc0, 1));
        mloc0 = fmaxf(mloc0, __shfl_xor_sync(0xffffffffu, mloc0, 2));
        mloc1 = fmaxf(mloc1, __shfl_xor_sync(0xffffffffu, mloc1, 1));
        mloc1 = fmaxf(mloc1, __shfl_xor_sync(0xffffffffu, mloc1, 2));

        float m_new0 = fmaxf(m_run0, mloc0);
        float m_new1 = fmaxf(m_run1, mloc1);
        float corr0 = ex2(m_run0 - m_new0);
        float corr1 = ex2(m_run1 - m_new1);
        m_run0 = m_new0; m_run1 = m_new1;

        float ps0 = 0.f, ps1 = 0.f;
        #pragma unroll
        for (int nt = 0; nt < 8; ++nt) {
            float p0 = ex2(sc[nt][0] - m_new0);
            float p1 = ex2(sc[nt][1] - m_new0);
            float p2 = ex2(sc[nt][2] - m_new1);
            float p3 = ex2(sc[nt][3] - m_new1);
            sc[nt][0] = p0; sc[nt][1] = p1; sc[nt][2] = p2; sc[nt][3] = p3;
            ps0 += p0 + p1; ps1 += p2 + p3;
        }
        ps0 += __shfl_xor_sync(0xffffffffu, ps0, 1);
        ps0 += __shfl_xor_sync(0xffffffffu, ps0, 2);
        ps1 += __shfl_xor_sync(0xffffffffu, ps1, 1);
        ps1 += __shfl_xor_sync(0xffffffffu, ps1, 2);
        l_run0 = l_run0 * corr0 + ps0;
        l_run1 = l_run1 * corr1 + ps1;

        #pragma unroll
        for (int nt = 0; nt < 8; ++nt) {
            o[nt][0] *= corr0; o[nt][1] *= corr0;
            o[nt][2] *= corr1; o[nt][3] *= corr1;
        }

        // ---- PV (fp16 P, 1 term) ----
        #pragma unroll
        for (int ks = 0; ks < 4; ++ks) {
            uint32_t ph[4];
            ph[0] = pack_h2(sc[2 * ks][0],     sc[2 * ks][1]);
            ph[1] = pack_h2(sc[2 * ks][2],     sc[2 * ks][3]);
            ph[2] = pack_h2(sc[2 * ks + 1][0], sc[2 * ks + 1][1]);
            ph[3] = pack_h2(sc[2 * ks + 1][2], sc[2 * ks + 1][3]);
            #pragma unroll
            for (int dp = 0; dp < 4; ++dp) {
                uint32_t vh[4];
                uint32_t voff = (uint32_t)((ks * 16 + ((lane >> 3) & 1) * 8 + (lane & 7)) * LROW
                                           + dp * 16 + lk) * 2;
                LDM4T(vh[0], vh[1], vh[2], vh[3], VHb + voff);
                MMA16816(o[2 * dp + 0], ph[0], ph[1], ph[2], ph[3], vh[0], vh[1]);
                MMA16816(o[2 * dp + 1], ph[0], ph[1], ph[2], ph[3], vh[2], vh[3]);
            }
        }

        __syncthreads();
        if (it + 2 < nkt) issueKV(it + 2);
    }

    // ---- write out ----
    float inv0 = 1.f / l_run0;
    float inv1 = 1.f / l_run1;
    const int cb = h * HD + 2 * (lane & 3);
    #pragma unroll
    for (int nt = 0; nt < 8; ++nt) {
        *(float2*)&out[(size_t)r0g * DM + cb + nt * 8] =
            make_float2(o[nt][0] * inv0, o[nt][1] * inv0);
        *(float2*)&out[(size_t)(r0g + 8) * DM + cb + nt * 8] =
            make_float2(o[nt][2] * inv1, o[nt][3] * inv1);
    }
}

// ---------------------------------------------------------------------------
extern "C" void kernel_launch(void* const* d_in, const int* in_sizes, int n_in,
                              void* d_out, int out_size) {
    const float* x = (const float*)d_in[0];    // [1, 4096, 1024]
    const float* w = (const float*)d_in[1];    // [1024, 3072]
    float* out = (float*)d_out;                // [1, 4096, 1024]

    prep_x_kernel<<<S_LEN * DM / 256, 256>>>(x);
    prep_w_kernel<<<dim3(N3 / 32, DM / 32), dim3(32, 8)>>>(w);

    const int gemm_smem = 2 * BUF_B;           // 110592 B
    cudaFuncSetAttribute(gemm_mma_kernel,
                         cudaFuncAttributeMaxDynamicSharedMemorySize, gemm_smem);
    gemm_mma_kernel<<<dim3(N3 / 128, S_LEN / 128), 256, gemm_smem>>>();

    const int attn_smem = BQ * LROW * 2 + 2 * 2 * KVTILE_B;   // 55296 B
    cudaFuncSetAttribute(attn_mma_kernel,
                         cudaFuncAttributeMaxDynamicSharedMemorySize, attn_smem);
    attn_mma_kernel<<<dim3(S_LEN / BQ, NHEADS), 256, attn_smem>>>(out);
}

// round 17
// speedup vs baseline: 5.6625x; 1.4963x over previous
#include <cuda_runtime.h>
#include <cuda_fp16.h>
#include <math.h>
#include <stdint.h>

#define S_LEN   4096
#define DM      1024
#define N3      3072
#define NHEADS  16
#define HD      64
#define WIN     512

// fp16 of x and w^T
__device__ __half g_Xh[S_LEN * DM];
__device__ __half g_Wh[N3 * DM];          // transposed: [n][k]
// fp16 kqv = x @ w_kqv  (cols 0..1023 K, 1024..2047 Q, 2048..3071 V)
__device__ __half g_C[S_LEN * N3];

// ---------------------------------------------------------------------------
// helpers
// ---------------------------------------------------------------------------
__device__ __forceinline__ uint32_t smem_u32(const void* p) {
    return (uint32_t)__cvta_generic_to_shared(p);
}

__device__ __forceinline__ void cp_async16(uint32_t dst, const void* src) {
    asm volatile("cp.async.cg.shared.global [%0], [%1], 16;" :: "r"(dst), "l"(src) : "memory");
}
#define CP_COMMIT() asm volatile("cp.async.commit_group;" ::: "memory")
#define CP_WAIT(n)  asm volatile("cp.async.wait_group %0;" :: "n"(n) : "memory")

#define LDM4(r0, r1, r2, r3, addr)                                            \
    asm volatile("ldmatrix.sync.aligned.m8n8.x4.shared.b16 {%0,%1,%2,%3}, [%4];" \
        : "=r"(r0), "=r"(r1), "=r"(r2), "=r"(r3) : "r"(addr))

#define LDM4T(r0, r1, r2, r3, addr)                                           \
    asm volatile("ldmatrix.sync.aligned.m8n8.x4.trans.shared.b16 {%0,%1,%2,%3}, [%4];" \
        : "=r"(r0), "=r"(r1), "=r"(r2), "=r"(r3) : "r"(addr))

#define MMA16816(d, a0, a1, a2, a3, b0, b1)                                   \
    asm volatile("mma.sync.aligned.m16n8k16.row.col.f32.f16.f16.f32 "         \
        "{%0,%1,%2,%3}, {%4,%5,%6,%7}, {%8,%9}, {%0,%1,%2,%3};"               \
        : "+f"((d)[0]), "+f"((d)[1]), "+f"((d)[2]), "+f"((d)[3])              \
        : "r"(a0), "r"(a1), "r"(a2), "r"(a3), "r"(b0), "r"(b1))

// hardware 2^x (MUFU.EX2); ftz flushes the -1e30 case to 0.
__device__ __forceinline__ float ex2(float x) {
    float r;
    asm("ex2.approx.ftz.f32 %0, %1;" : "=f"(r) : "f"(x));
    return r;
}

__device__ __forceinline__ uint32_t pack_h2(float a, float b) {
    __half2 h = __floats2half2_rn(a, b);
    return *(uint32_t*)&h;
}

// ---------------------------------------------------------------------------
// Prep
// ---------------------------------------------------------------------------
__global__ void prep_x_kernel(const float* __restrict__ x) {
    int idx = blockIdx.x * 256 + threadIdx.x;
    g_Xh[idx] = __float2half_rn(x[idx]);
}

__global__ void prep_w_kernel(const float* __restrict__ w) {
    __shared__ float t[32][33];
    int n0 = blockIdx.x * 32, k0 = blockIdx.y * 32;
    int tx = threadIdx.x, ty = threadIdx.y;
    for (int r = ty; r < 32; r += 8)
        t[r][tx] = w[(size_t)(k0 + r) * N3 + n0 + tx];
    __syncthreads();
    for (int r = ty; r < 32; r += 8)
        g_Wh[(size_t)(n0 + r) * DM + k0 + tx] = __float2half_rn(t[tx][r]);
}

// ---------------------------------------------------------------------------
// GEMM: C = X @ W via single-term fp16 mma.sync, fp32 accum.
// 128x128 tile / CTA, 8 warps (64x32), K chunks of 64, cp.async double buffer.
// ---------------------------------------------------------------------------
#define LROW 72
#define ARR_B   (128 * LROW * 2)      // 18432 B per array
#define BUF_B   (2 * ARR_B)           // 36864 B per buffer (Xh, Wh)

__global__ __launch_bounds__(256, 2)
void gemm_mma_kernel() {
    extern __shared__ char dsm[];
    const uint32_t sb = smem_u32(dsm);

    const int tid  = threadIdx.x;
    const int lane = tid & 31;
    const int w    = tid >> 5;
    const int m0   = blockIdx.y * 128;
    const int n0   = blockIdx.x * 128;
    const int wm   = (w >> 2) * 64;
    const int wn   = (w & 3) * 32;

    auto issue = [&](int buf, int k0) {
        uint32_t base = sb + buf * BUF_B;
        #pragma unroll
        for (int it = 0; it < 8; ++it) {
            int cid = tid + it * 256;            // 0..2047
            int arr = cid >> 10;                 // 0:Xh 1:Wh
            int row = (cid >> 3) & 127;
            int c8  = (cid & 7) * 8;
            uint32_t so = base + arr * ARR_B + (uint32_t)(row * LROW + c8) * 2;
            const __half* src = (arr == 0) ? &g_Xh[(size_t)(m0 + row) * DM + k0 + c8]
                                           : &g_Wh[(size_t)(n0 + row) * DM + k0 + c8];
            cp_async16(so, src);
        }
        CP_COMMIT();
    };

    float acc[4][4][4];
    #pragma unroll
    for (int i = 0; i < 4; ++i)
        #pragma unroll
        for (int j = 0; j < 4; ++j)
            #pragma unroll
            for (int r = 0; r < 4; ++r) acc[i][j][r] = 0.f;

    issue(0, 0);
    issue(1, 64);

    const int lrow = lane & 15;
    const int lk   = (lane >> 4) * 8;

    for (int c = 0; c < 16; ++c) {
        if (c < 14) { CP_WAIT(1); } else { CP_WAIT(0); }
        __syncthreads();

        const uint32_t bufb = sb + (c & 1) * BUF_B;
        const uint32_t xhB = bufb;
        const uint32_t whB = bufb + ARR_B;

        #pragma unroll
        for (int ks = 0; ks < 4; ++ks) {
            const int k0 = ks * 16;
            uint32_t ah[4][4], bh[2][4];
            #pragma unroll
            for (int mt = 0; mt < 4; ++mt) {
                uint32_t off = (uint32_t)((wm + mt * 16 + lrow) * LROW + k0 + lk) * 2;
                LDM4(ah[mt][0], ah[mt][1], ah[mt][2], ah[mt][3], xhB + off);
            }
            #pragma unroll
            for (int nt2 = 0; nt2 < 2; ++nt2) {
                uint32_t off = (uint32_t)((wn + nt2 * 16 + lrow) * LROW + k0 + lk) * 2;
                LDM4(bh[nt2][0], bh[nt2][1], bh[nt2][2], bh[nt2][3], whB + off);
            }
            #pragma unroll
            for (int mt = 0; mt < 4; ++mt) {
                #pragma unroll
                for (int nt2 = 0; nt2 < 2; ++nt2) {
                    MMA16816(acc[mt][nt2 * 2 + 0], ah[mt][0], ah[mt][1], ah[mt][2], ah[mt][3],
                             bh[nt2][0], bh[nt2][2]);
                    MMA16816(acc[mt][nt2 * 2 + 1], ah[mt][0], ah[mt][1], ah[mt][2], ah[mt][3],
                             bh[nt2][1], bh[nt2][3]);
                }
            }
        }
        __syncthreads();
        if (c + 2 < 16) issue((c & 1), (c + 2) * 64);
    }

    // epilogue: fp32 acc -> fp16 C
    const int er = lane >> 2;
    const int ec = (lane & 3) * 2;
    #pragma unroll
    for (int mt = 0; mt < 4; ++mt) {
        #pragma unroll
        for (int nt = 0; nt < 4; ++nt) {
            int row = m0 + wm + mt * 16 + er;
            int col = n0 + wn + nt * 8 + ec;
            __half2 v01 = __floats2half2_rn(acc[mt][nt][0], acc[mt][nt][1]);
            __half2 v23 = __floats2half2_rn(acc[mt][nt][2], acc[mt][nt][3]);
            *(__half2*)&g_C[(size_t)row * N3 + col] = v01;
            *(__half2*)&g_C[(size_t)(row + 8) * N3 + col] = v23;
        }
    }
}

// ---------------------------------------------------------------------------
// Attention: FA2-style fp16 mma.sync, 1-term QK and PV, MUFU softmax (base-2).
// CTA = (128 q-rows, head). 8 warps x 16 q-rows. Key tiles of 64, dbl-buffered.
// ---------------------------------------------------------------------------
#define BQ 128
#define BK 64
#define KVTILE_B (BK * LROW * 2)     // 9216 B per array (Kh, Vh)

__global__ __launch_bounds__(256, 2)
void attn_mma_kernel(float* __restrict__ out) {
    extern __shared__ char sm[];
    const uint32_t sb  = smem_u32(sm);
    const uint32_t QHb = sb;
    const uint32_t KV0 = sb + BQ * LROW * 2;       // stage s: KV0 + s*2*KVTILE_B

    const int tid  = threadIdx.x;
    const int lane = tid & 31;
    const int w    = tid >> 5;
    const int wq   = w * 16;
    const int h    = blockIdx.y;
    const int q0   = blockIdx.x * BQ;
    const float slope2 = exp2f(-0.5f * (float)(h + 1)) * 1.44269504f;
    const float C1     = 1.44269504f / 32.0f;

    // Q load: 1024 x 16B chunks
    #pragma unroll
    for (int k = 0; k < 4; ++k) {
        int cid = tid + 256 * k;
        int r   = cid >> 3;
        int c8  = (cid & 7) * 8;
        cp_async16(QHb + (uint32_t)(r * LROW + c8) * 2,
                   &g_C[(size_t)(q0 + r) * N3 + DM + h * HD + c8]);
    }

    const int kt_lo = max(0, (q0 >> 6) - 8);
    const int kt_hi = (q0 >> 6) + 1;
    const int nkt   = kt_hi - kt_lo + 1;

    auto issueKV = [&](int idx) {
        int jb = (kt_lo + idx) * BK;
        uint32_t base = KV0 + (idx & 1) * 2 * KVTILE_B;
        #pragma unroll
        for (int k = 0; k < 4; ++k) {
            int cid = tid + 256 * k;
            int arr = cid >> 9;                  // 0:Kh 1:Vh
            int r   = (cid >> 3) & 63;
            int c8  = (cid & 7) * 8;
            int colbase = (arr ? 2 * DM : 0) + h * HD;
            cp_async16(base + arr * KVTILE_B + (uint32_t)(r * LROW + c8) * 2,
                       &g_C[(size_t)(jb + r) * N3 + colbase + c8]);
        }
        CP_COMMIT();
    };

    issueKV(0);
    if (nkt > 1) issueKV(1);

    float o[8][4];
    #pragma unroll
    for (int i = 0; i < 8; ++i)
        #pragma unroll
        for (int j = 0; j < 4; ++j) o[i][j] = 0.f;
    float m_run0 = -1e30f, m_run1 = -1e30f;
    float l_run0 = 0.f, l_run1 = 0.f;

    const int r0g   = q0 + wq + (lane >> 2);
    const int lrow  = lane & 15;
    const int lk    = (lane >> 4) * 8;

    for (int it = 0; it < nkt; ++it) {
        if (it + 1 < nkt) { CP_WAIT(1); } else { CP_WAIT(0); }
        __syncthreads();
        const uint32_t kb  = KV0 + (it & 1) * 2 * KVTILE_B;
        const uint32_t KHb = kb, VHb = kb + KVTILE_B;
        const int jb = (kt_lo + it) * BK;

        // ---- QK^T (1 term) ----
        float sc[8][4];
        #pragma unroll
        for (int i = 0; i < 8; ++i)
            #pragma unroll
            for (int j = 0; j < 4; ++j) sc[i][j] = 0.f;

        #pragma unroll
        for (int ks = 0; ks < 4; ++ks) {
            uint32_t qh[4];
            uint32_t qoff = (uint32_t)((wq + lrow) * LROW + ks * 16 + lk) * 2;
            LDM4(qh[0], qh[1], qh[2], qh[3], QHb + qoff);
            #pragma unroll
            for (int np = 0; np < 4; ++np) {
                uint32_t bh[4];
                uint32_t koff = (uint32_t)((np * 16 + lrow) * LROW + ks * 16 + lk) * 2;
                LDM4(bh[0], bh[1], bh[2], bh[3], KHb + koff);
                MMA16816(sc[2 * np + 0], qh[0], qh[1], qh[2], qh[3], bh[0], bh[2]);
                MMA16816(sc[2 * np + 1], qh[0], qh[1], qh[2], qh[3], bh[1], bh[3]);
            }
        }

        // ---- bias + mask + online softmax (base-2, MUFU ex2) ----
        const int jbase = jb + 2 * (lane & 3);
        float mloc0 = -1e30f, mloc1 = -1e30f;
        #pragma unroll
        for (int nt = 0; nt < 8; ++nt) {
            #pragma unroll
            for (int e = 0; e < 4; ++e) {
                int j  = jbase + nt * 8 + (e & 1);
                int i  = r0g + ((e >> 1) << 3);
                int jr = j - i;                      // valid iff -512 <= jr <= 0
                float t = fmaf(sc[nt][e], C1, slope2 * (float)jr);
                bool valid = (jr <= 0) && (jr >= -WIN);
                t = valid ? t : -1e30f;
                sc[nt][e] = t;
                if (e < 2) mloc0 = fmaxf(mloc0, t);
                else       mloc1 = fmaxf(mloc1, t);
            }
        }
        mloc0 = fmaxf(mloc0, __shfl_xor_sync(0xffffffffu, mloc0, 1));
        mloc0 = fmaxf(mloc0, __shfl_xor_sync(0xffffffffu, mloc0, 2));
        mloc1 = fmaxf(mloc1, __shfl_xor_sync(0xffffffffu, mloc1, 1));
        mloc1 = fmaxf(mloc1, __shfl_xor_sync(0xffffffffu, mloc1, 2));

        float m_new0 = fmaxf(m_run0, mloc0);
        float m_new1 = fmaxf(m_run1, mloc1);
        float corr0 = ex2(m_run0 - m_new0);
        float corr1 = ex2(m_run1 - m_new1);
        m_run0 = m_new0; m_run1 = m_new1;

        float ps0 = 0.f, ps1 = 0.f;
        #pragma unroll
        for (int nt = 0; nt < 8; ++nt) {
            float p0 = ex2(sc[nt][0] - m_new0);
            float p1 = ex2(sc[nt][1] - m_new0);
            float p2 = ex2(sc[nt][2] - m_new1);
            float p3 = ex2(sc[nt][3] - m_new1);
            sc[nt][0] = p0; sc[nt][1] = p1; sc[nt][2] = p2; sc[nt][3] = p3;
            ps0 += p0 + p1; ps1 += p2 + p3;
        }
        ps0 += __shfl_xor_sync(0xffffffffu, ps0, 1);
        ps0 += __shfl_xor_sync(0xffffffffu, ps0, 2);
        ps1 += __shfl_xor_sync(0xffffffffu, ps1, 1);
        ps1 += __shfl_xor_sync(0xffffffffu, ps1, 2);
        l_run0 = l_run0 * corr0 + ps0;
        l_run1 = l_run1 * corr1 + ps1;

        #pragma unroll
        for (int nt = 0; nt < 8; ++nt) {
            o[nt][0] *= corr0; o[nt][1] *= corr0;
            o[nt][2] *= corr1; o[nt][3] *= corr1;
        }

        // ---- PV (fp16 P, 1 term) ----
        #pragma unroll
        for (int ks = 0; ks < 4; ++ks) {
            uint32_t ph[4];
            ph[0] = pack_h2(sc[2 * ks][0],     sc[2 * ks][1]);
            ph[1] = pack_h2(sc[2 * ks][2],     sc[2 * ks][3]);
            ph[2] = pack_h2(sc[2 * ks + 1][0], sc[2 * ks + 1][1]);
            ph[3] = pack_h2(sc[2 * ks + 1][2], sc[2 * ks + 1][3]);
            #pragma unroll
            for (int dp = 0; dp < 4; ++dp) {
                uint32_t vh[4];
                uint32_t voff = (uint32_t)((ks * 16 + ((lane >> 3) & 1) * 8 + (lane & 7)) * LROW
                                           + dp * 16 + lk) * 2;
                LDM4T(vh[0], vh[1], vh[2], vh[3], VHb + voff);
                MMA16816(o[2 * dp + 0], ph[0], ph[1], ph[2], ph[3], vh[0], vh[1]);
                MMA16816(o[2 * dp + 1], ph[0], ph[1], ph[2], ph[3], vh[2], vh[3]);
            }
        }

        __syncthreads();
        if (it + 2 < nkt) issueKV(it + 2);
    }

    // ---- write out ----
    float inv0 = 1.f / l_run0;
    float inv1 = 1.f / l_run1;
    const int cb = h * HD + 2 * (lane & 3);
    #pragma unroll
    for (int nt = 0; nt < 8; ++nt) {
        *(float2*)&out[(size_t)r0g * DM + cb + nt * 8] =
            make_float2(o[nt][0] * inv0, o[nt][1] * inv0);
        *(float2*)&out[(size_t)(r0g + 8) * DM + cb + nt * 8] =
            make_float2(o[nt][2] * inv1, o[nt][3] * inv1);
    }
}

// ---------------------------------------------------------------------------
extern "C" void kernel_launch(void* const* d_in, const int* in_sizes, int n_in,
                              void* d_out, int out_size) {
    const float* x = (const float*)d_in[0];    // [1, 4096, 1024]
    const float* w = (const float*)d_in[1];    // [1024, 3072]
    float* out = (float*)d_out;                // [1, 4096, 1024]

    prep_x_kernel<<<S_LEN * DM / 256, 256>>>(x);
    prep_w_kernel<<<dim3(N3 / 32, DM / 32), dim3(32, 8)>>>(w);

    const int gemm_smem = 2 * BUF_B;           // 73728 B
    cudaFuncSetAttribute(gemm_mma_kernel,
                         cudaFuncAttributeMaxDynamicSharedMemorySize, gemm_smem);
    gemm_mma_kernel<<<dim3(N3 / 128, S_LEN / 128), 256, gemm_smem>>>();

    const int attn_smem = BQ * LROW * 2 + 2 * 2 * KVTILE_B;   // 55296 B
    cudaFuncSetAttribute(attn_mma_kernel,
                         cudaFuncAttributeMaxDynamicSharedMemorySize, attn_smem);
    attn_mma_kernel<<<dim3(S_LEN / BQ, NHEADS), 256, attn_smem>>>(out);
}